// round 1
// baseline (speedup 1.0000x reference)
#include <cuda_runtime.h>
#include <cuda_bf16.h>

// Problem constants
constexpr int B_ = 16, C_ = 128, H_ = 72, W_ = 200, K_ = 9, PAD_ = 4;
constexpr int CS = H_ * W_;      // channel stride (14400) — identical in transposed layout
constexpr size_t BS = (size_t)C_ * CS;    // batch stride
constexpr size_t TOTAL = (size_t)B_ * BS; // 29,491,200 elements

// Tiling
constexpr int TM = 32;   // c_out tile
constexpr int TN = 32;   // j tile (conv-axis positions)
constexpr int CI = 16;   // c_in chunk
constexpr int NT = 128;  // threads per CTA

// Scratch buffer for the (B,C,W,H)-transposed layout (device global: no allocs allowed)
__device__ float g_tbuf[TOTAL];

// One scan step:  cur[b,co,j] += relu( sum_{ci,k} w[co,ci,k] * prev[b,ci,j+k-4] )
// base points at a (B, C, NumRows, L) buffer with row r of slab (b,c) at offset r*L.
__global__ void step_kernel(float* __restrict__ base, const float* __restrict__ w,
                            int prevIdx, int curIdx, int L) {
    __shared__ __align__(16) float p_s[CI][TN + 8];   // prev-row tile with K-1 halo
    __shared__ float w_s[CI * K_][TM + 1];            // [(ci*9+k)][co], padded vs bank conflicts

    const int t = threadIdx.x;
    const int jbase = blockIdx.x * TN;
    const int cobase = blockIdx.y * TM;
    const int b = blockIdx.z;

    const float* __restrict__ prow = base + (size_t)b * BS + (size_t)prevIdx * L;
    float* __restrict__ crow       = base + (size_t)b * BS + (size_t)curIdx * L;

    const int cf = t & 15;   // 16 c_out pairs
    const int jf = t >> 4;   // 8 j quads

    float acc[2][4] = {{0.f, 0.f, 0.f, 0.f}, {0.f, 0.f, 0.f, 0.f}};

    #pragma unroll 1
    for (int cc = 0; cc < C_; cc += CI) {
        __syncthreads();
        // ---- load prev tile (CI x (TN+8)) = 640 elems, 5 per thread ----
        #pragma unroll
        for (int i = 0; i < (CI * (TN + 8)) / NT; ++i) {
            int e = t + i * NT;
            int ci = e / (TN + 8);
            int x  = e % (TN + 8);
            int gj = jbase + x - PAD_;
            float v = 0.f;
            if (gj >= 0 && gj < L) v = prow[(size_t)(cc + ci) * CS + gj];
            p_s[ci][x] = v;
        }
        // ---- load weight chunk (TM x CI x K_) = 4608 elems, 36 per thread ----
        // global layout w[co][ci][k]; chunk rows are contiguous 144-float runs per co
        const float* wblk = w + (size_t)cobase * (C_ * K_) + (size_t)cc * K_;
        #pragma unroll
        for (int i = 0; i < (TM * CI * K_) / NT; ++i) {
            int e = t + i * NT;
            int co = e / (CI * K_);
            int r  = e % (CI * K_);       // ci*9 + k
            w_s[r][co] = wblk[(size_t)co * (C_ * K_) + r];
        }
        __syncthreads();

        #pragma unroll
        for (int ci = 0; ci < CI; ++ci) {
            // 12-wide sliding window of prev values for this thread's 4 j's
            const float4 v0 = *(const float4*)&p_s[ci][jf * 4 + 0];
            const float4 v1 = *(const float4*)&p_s[ci][jf * 4 + 4];
            const float4 v2 = *(const float4*)&p_s[ci][jf * 4 + 8];
            const float p[12] = {v0.x, v0.y, v0.z, v0.w,
                                 v1.x, v1.y, v1.z, v1.w,
                                 v2.x, v2.y, v2.z, v2.w};
            #pragma unroll
            for (int k = 0; k < K_; ++k) {
                const float w0 = w_s[ci * K_ + k][cf * 2 + 0];
                const float w1 = w_s[ci * K_ + k][cf * 2 + 1];
                #pragma unroll
                for (int n = 0; n < 4; ++n) {
                    acc[0][n] = fmaf(w0, p[k + n], acc[0][n]);
                    acc[1][n] = fmaf(w1, p[k + n], acc[1][n]);
                }
            }
        }
    }

    // ---- epilogue: cur += relu(acc) (each element owned by exactly one thread) ----
    #pragma unroll
    for (int m = 0; m < 2; ++m) {
        const int co = cobase + cf * 2 + m;
        #pragma unroll
        for (int n = 0; n < 4; ++n) {
            const int j = jbase + jf * 4 + n;
            if (j < L) {
                const size_t off = (size_t)co * CS + j;
                const float r = acc[m][n];
                crow[off] += (r > 0.f ? r : 0.f);
            }
        }
    }
}

// Transpose per (b,c) slab: src slab R x Cc (row-major) -> dst slab Cc x R.
__global__ void transpose_kernel(const float* __restrict__ src, float* __restrict__ dst,
                                 int R, int Cc) {
    __shared__ float tile[32][33];
    const size_t slab = blockIdx.z;
    const float* s = src + slab * (size_t)(R * Cc);
    float* d       = dst + slab * (size_t)(R * Cc);
    const int c0 = blockIdx.x * 32;
    const int r0 = blockIdx.y * 32;

    #pragma unroll
    for (int i = 0; i < 32; i += 8) {
        int r = r0 + threadIdx.y + i;
        int c = c0 + threadIdx.x;
        if (r < R && c < Cc) tile[threadIdx.y + i][threadIdx.x] = s[(size_t)r * Cc + c];
    }
    __syncthreads();
    #pragma unroll
    for (int i = 0; i < 32; i += 8) {
        int c = c0 + threadIdx.y + i;  // dst row
        int r = r0 + threadIdx.x;      // dst col
        if (r < R && c < Cc) d[(size_t)c * R + r] = tile[threadIdx.x][threadIdx.y + i];
    }
}

extern "C" void kernel_launch(void* const* d_in, const int* in_sizes, int n_in,
                              void* d_out, int out_size) {
    const float* x  = (const float*)d_in[0];
    const float* wd = (const float*)d_in[1];
    const float* wu = (const float*)d_in[2];
    const float* wr = (const float*)d_in[3];
    const float* wl = (const float*)d_in[4];
    float* out = (float*)d_out;

    float* tbuf = nullptr;
    cudaGetSymbolAddress((void**)&tbuf, g_tbuf);

    // Initialize working buffer with x (scan runs in-place on d_out)
    cudaMemcpyAsync(out, x, TOTAL * sizeof(float), cudaMemcpyDeviceToDevice);

    const dim3 blk(NT);

    // ---- down / up: conv along W (contiguous), steps along H ----
    const dim3 gw((W_ + TN - 1) / TN, C_ / TM, B_);
    for (int h = 1; h < H_; ++h)
        step_kernel<<<gw, blk>>>(out, wd, h - 1, h, W_);
    for (int h = H_ - 2; h >= 0; --h)
        step_kernel<<<gw, blk>>>(out, wu, h + 1, h, W_);

    // ---- transpose (B,C,H,W) -> (B,C,W,H) so conv along H becomes contiguous ----
    const dim3 tb(32, 8);
    const dim3 tg1((W_ + 31) / 32, (H_ + 31) / 32, B_ * C_);
    transpose_kernel<<<tg1, tb>>>(out, tbuf, H_, W_);

    // ---- right / left: conv along H (now contiguous), steps along W ----
    const dim3 gh((H_ + TN - 1) / TN, C_ / TM, B_);
    for (int w = 1; w < W_; ++w)
        step_kernel<<<gh, blk>>>(tbuf, wr, w - 1, w, H_);
    for (int w = W_ - 2; w >= 0; --w)
        step_kernel<<<gh, blk>>>(tbuf, wl, w + 1, w, H_);

    // ---- transpose back (B,C,W,H) -> (B,C,H,W) into d_out ----
    const dim3 tg2((H_ + 31) / 32, (W_ + 31) / 32, B_ * C_);
    transpose_kernel<<<tg2, tb>>>(tbuf, out, W_, H_);
}